// round 3
// baseline (speedup 1.0000x reference)
#include <cuda_runtime.h>

#define T 64
#define S_LEN 1024
#define BATCH 512
#define START_TAG 62
#define STOP_TAG 63
#define NEG_INF_C (-10000.0f)

__device__ float g_diff[BATCH];

__global__ __launch_bounds__(32) void crf_warp_kernel(
    const float* __restrict__ feats,
    const float* __restrict__ trans,
    const void* __restrict__ tags_raw,
    const int* __restrict__ mask)
{
    const int b = blockIdx.x;
    const int l = threadIdx.x;      // 0..31
    const int t0 = l;
    const int t1 = l + 32;

    __shared__ __align__(16) float p_sh[T];

    // Precompute exp(trans) rows owned by this thread (rows t0 and t1).
    float E0[T], E1[T];
#pragma unroll
    for (int j = 0; j < T; j++) {
        E0[j] = __expf(trans[t0 * T + j]);
        E1[j] = __expf(trans[t1 * T + j]);
    }

    const float* fb = feats + (size_t)b * S_LEN * T;
    const int*   mb = mask + (size_t)b * S_LEN;

    float fv0 = (t0 == START_TAG) ? 0.0f : NEG_INF_C;
    float fv1 = (t1 == START_TAG) ? 0.0f : NEG_INF_C;

    // 2-deep prefetch pipeline for feats/mask
    float fA0 = fb[t0];
    float fA1 = fb[t1];
    int   mA  = mb[0];
    float fB0 = fb[T + t0];
    float fB1 = fb[T + t1];
    int   mB  = mb[1];

    for (int s = 0; s < S_LEN; s++) {
        float f0 = fA0, f1 = fA1;
        int   mk = mA;
        fA0 = fB0; fA1 = fB1; mA = mB;
        int s2 = s + 2;
        if (s2 < S_LEN) {
            fB0 = fb[s2 * T + t0];
            fB1 = fb[s2 * T + t1];
            mB  = mb[s2];
        }

        // m = max_j fv[j] (warp reduce over 64 values, 2 per lane)
        float m = fmaxf(fv0, fv1);
#pragma unroll
        for (int off = 16; off > 0; off >>= 1)
            m = fmaxf(m, __shfl_xor_sync(0xffffffffu, m, off));

        float p0 = __expf(fv0 - m);
        float p1 = __expf(fv1 - m);
        p_sh[t0] = p0;
        p_sh[t1] = p1;
        __syncwarp();

        const float4* p4 = (const float4*)p_sh;
        float a0 = 0.f, a1 = 0.f, a2 = 0.f, a3 = 0.f;
        float c0 = 0.f, c1 = 0.f, c2 = 0.f, c3 = 0.f;
#pragma unroll
        for (int jj = 0; jj < 16; jj++) {
            float4 pv = p4[jj];
            a0 = fmaf(E0[4 * jj + 0], pv.x, a0);
            a1 = fmaf(E0[4 * jj + 1], pv.y, a1);
            a2 = fmaf(E0[4 * jj + 2], pv.z, a2);
            a3 = fmaf(E0[4 * jj + 3], pv.w, a3);
            c0 = fmaf(E1[4 * jj + 0], pv.x, c0);
            c1 = fmaf(E1[4 * jj + 1], pv.y, c1);
            c2 = fmaf(E1[4 * jj + 2], pv.z, c2);
            c3 = fmaf(E1[4 * jj + 3], pv.w, c3);
        }
        __syncwarp();   // all lanes done reading p_sh before next-iter stores

        float acc0 = fmaxf((a0 + a1) + (a2 + a3), 1e-30f);
        float acc1 = fmaxf((c0 + c1) + (c2 + c3), 1e-30f);
        float n0 = f0 + m + __logf(acc0);
        float n1 = f1 + m + __logf(acc1);
        if (mk) { fv0 = n0; fv1 = n1; }
    }

    // Terminal: forward_score = lse_i(fv[i] + trans[STOP, i])
    float tm0 = fv0 + trans[STOP_TAG * T + t0];
    float tm1 = fv1 + trans[STOP_TAG * T + t1];
    float m2 = fmaxf(tm0, tm1);
#pragma unroll
    for (int off = 16; off > 0; off >>= 1)
        m2 = fmaxf(m2, __shfl_xor_sync(0xffffffffu, m2, off));
    float ssum = __expf(tm0 - m2) + __expf(tm1 - m2);
#pragma unroll
    for (int off = 16; off > 0; off >>= 1)
        ssum += __shfl_xor_sync(0xffffffffu, ssum, off);
    float fscore = m2 + __logf(ssum);

    // -------- tags dtype autodetect (int64 vs int32) --------
    // If tags are int64 (values 0..61 >= 0), every odd 32-bit word is 0.
    // If int32, odd words are tags themselves (all-zero prob ~ 62^-128).
    const int* tags32 = (const int*)tags_raw;
    int hi_or = 0;
    for (int i = l; i < 128; i += 32) hi_or |= tags32[2 * i + 1];
#pragma unroll
    for (int off = 16; off > 0; off >>= 1)
        hi_or |= __shfl_xor_sync(0xffffffffu, hi_or, off);
    const bool is64 = (hi_or == 0);
    const long long* tags64 = (const long long*)tags_raw;
    const size_t tbase = (size_t)b * S_LEN;

    // Gold path score (parallel gather over s, lane-strided)
    float gsum = 0.f;
    int   mcnt = 0;
    for (int s = l; s < S_LEN; s += 32) {
        int cur  = is64 ? (int)tags64[tbase + s] : tags32[tbase + s];
        int prev = (s == 0) ? START_TAG
                            : (is64 ? (int)tags64[tbase + s - 1] : tags32[tbase + s - 1]);
        int mk   = mb[s];
        if (mk) {
            gsum += fb[s * T + cur] + trans[cur * T + prev];
            mcnt++;
        }
    }
#pragma unroll
    for (int off = 16; off > 0; off >>= 1) {
        gsum += __shfl_xor_sync(0xffffffffu, gsum, off);
        mcnt += __shfl_xor_sync(0xffffffffu, mcnt, off);
    }
    if (l == 0) {
        int last_tag;
        if (mcnt == 0) last_tag = START_TAG;
        else last_tag = is64 ? (int)tags64[tbase + mcnt - 1] : tags32[tbase + mcnt - 1];
        float gold = gsum + trans[STOP_TAG * T + last_tag];
        g_diff[b] = fscore - gold;
    }
}

__global__ void crf_reduce_kernel(float* __restrict__ out)
{
    __shared__ float sm[BATCH];
    int t = threadIdx.x;
    sm[t] = g_diff[t];
    __syncthreads();
    for (int st = BATCH / 2; st > 0; st >>= 1) {
        if (t < st) sm[t] += sm[t + st];
        __syncthreads();
    }
    if (t == 0) out[0] = sm[0] * (1.0f / (float)BATCH);
}

extern "C" void kernel_launch(void* const* d_in, const int* in_sizes, int n_in,
                              void* d_out, int out_size)
{
    const float* feats = (const float*)d_in[0];
    const float* trans = (const float*)d_in[1];
    const void*  tags  = (const void*)d_in[2];
    const int*   mask  = (const int*)d_in[3];
    float* out = (float*)d_out;

    crf_warp_kernel<<<BATCH, 32>>>(feats, trans, tags, mask);
    crf_reduce_kernel<<<1, BATCH>>>(out);
}